// round 11
// baseline (speedup 1.0000x reference)
#include <cuda_runtime.h>

// HaversineSmoothedLoss — R9 inner loop, RPB=2 for 10 blocks/SM occupancy.
//   a  = (1 - u1·u2)/2             (unit 3-vectors; no per-pair trig)
//   w  = exp2( sqrt(|a|) * (KL + KL3*a) )   1-term asin correction
//   loss_b = log(Z_b) - (Σ w·x)/S_b ,  Z = Σ e^x, S = Σ w
//
// K0: celltab unit vectors (once).
// K1: 2048 blocks (128 thr, 10 blocks/SM via reg cap 51) = 256 row-groups
//     (2 rows) × 8 chunks (4096 cells). 8 iters/thread, 5 front-batched
//     LDG.128 per iter, branchless 12-inst/elem loop.
//     Last block (arrival counter) reduces partials to the loss.

#define C_CELLS 32768
#define B_ROWS  512
#define RPB     2
#define SPLIT   8
#define CHUNK   (C_CELLS / SPLIT)          // 4096
#define THREADS 128
#define NWARPS  (THREADS / 32)             // 4
#define ITERS   (CHUNK / (4 * THREADS))    // 8
#define GRID    ((B_ROWS / RPB) * SPLIT)   // 2048

__device__ float d_ux[C_CELLS];
__device__ float d_uy[C_CELLS];
__device__ float d_uz[C_CELLS];
__device__ float d_prow[3][B_ROWS];        // -0.5 * row unit vectors
__device__ float d_pZ[B_ROWS * SPLIT];
__device__ float d_pS[B_ROWS * SPLIT];
__device__ float d_pW[B_ROWS * SPLIT];
__device__ unsigned int d_ctr = 0;

__device__ __forceinline__ float fsqrt_ap(float a) {
    float r; asm("sqrt.approx.f32 %0, %1;" : "=f"(r) : "f"(a)); return r;
}
__device__ __forceinline__ float fexp2_ap(float a) {
    float r; asm("ex2.approx.f32 %0, %1;" : "=f"(r) : "f"(a)); return r;
}

__global__ void precompute(const float* __restrict__ geo,
                           const float* __restrict__ latlon) {
    const float d2r = 0.017453292519943295f;
    int i = blockIdx.x * blockDim.x + threadIdx.x;
    if (i < C_CELLS) {
        float lat = geo[2 * i]     * d2r;
        float lon = geo[2 * i + 1] * d2r;
        float sl, cl, so, co;
        sincosf(lat, &sl, &cl);
        sincosf(lon, &so, &co);
        d_ux[i] = sl;
        d_uy[i] = cl * so;
        d_uz[i] = cl * co;
    }
    if (i < B_ROWS) {
        float lat = latlon[2 * i]     * d2r;
        float lon = latlon[2 * i + 1] * d2r;
        float sl, cl, so, co;
        sincosf(lat, &sl, &cl);
        sincosf(lon, &so, &co);
        d_prow[0][i] = -0.5f * sl;
        d_prow[1][i] = -0.5f * cl * so;
        d_prow[2][i] = -0.5f * cl * co;
    }
}

__global__ __launch_bounds__(THREADS, 10)
void main_kernel(const float* __restrict__ logits,
                 float* __restrict__ out) {
    const int bx    = blockIdx.x;
    const int rg    = bx >> 3;             // row group 0..255
    const int ch    = bx & (SPLIT - 1);    // chunk 0..7
    const int row0  = rg * RPB;
    const int tid   = threadIdx.x;
    const int qbase = (ch * CHUNK) >> 2;   // float4 quad base of this chunk

    const float LOG2E = 1.4426950408889634f;
    const float KL  = -245.104328f;        // -(2*6371/75)*log2(e)
    const float KL3 = -40.8507213f;        // KL/6   (imm multiplier -> FFMA-imm, rt 1)

    // Row uniforms (block-uniform loads).
    float nx[RPB], ny[RPB], nz[RPB];
    #pragma unroll
    for (int r = 0; r < RPB; r++) {
        nx[r] = d_prow[0][row0 + r];
        ny[r] = d_prow[1][row0 + r];
        nz[r] = d_prow[2][row0 + r];
    }

    const float4* __restrict__ lg4 = (const float4*)logits;
    const float4* __restrict__ ux4 = (const float4*)d_ux;
    const float4* __restrict__ uy4 = (const float4*)d_uy;
    const float4* __restrict__ uz4 = (const float4*)d_uz;

    float Z[RPB], S[RPB], WX[RPB];
    #pragma unroll
    for (int r = 0; r < RPB; r++) { Z[r] = 0.f; S[r] = 0.f; WX[r] = 0.f; }

    #pragma unroll 1
    for (int it = 0; it < ITERS; it++) {
        const int q = qbase + it * THREADS + tid;

        // Front-batch all 5 LDG.128 for this iteration.
        float4 xr[RPB];
        #pragma unroll
        for (int r = 0; r < RPB; r++)
            xr[r] = __ldg(lg4 + (size_t)(row0 + r) * (C_CELLS / 4) + q);
        const float4 gx = __ldg(ux4 + q);
        const float4 gy = __ldg(uy4 + q);
        const float4 gz = __ldg(uz4 + q);

        const float gxs[4] = {gx.x, gx.y, gx.z, gx.w};
        const float gys[4] = {gy.x, gy.y, gy.z, gy.w};
        const float gzs[4] = {gz.x, gz.y, gz.z, gz.w};

        #pragma unroll
        for (int r = 0; r < RPB; r++) {
            const float xs[4] = {xr[r].x, xr[r].y, xr[r].z, xr[r].w};
            #pragma unroll
            for (int k = 0; k < 4; k++) {
                const float x = xs[k];
                Z[r] += fexp2_ap(x * LOG2E);
                float a = fmaf(nx[r], gxs[k], fmaf(ny[r], gys[k], fmaf(nz[r], gzs[k], 0.5f)));
                float s  = fsqrt_ap(fabsf(a));       // |a|: free operand modifier
                float qq = fmaf(a, KL3, KL);         // 1-term asin correction (FFMA-imm)
                float w  = fexp2_ap(s * qq);         // underflows to 0 for far cells
                S[r]  += w;
                WX[r]  = fmaf(w, x, WX[r]);
            }
        }
    }

    // ---- Block reduction of 6 accumulators (deterministic tree) ----
    float acc[3 * RPB];
    #pragma unroll
    for (int r = 0; r < RPB; r++) {
        acc[r * 3 + 0] = Z[r]; acc[r * 3 + 1] = S[r]; acc[r * 3 + 2] = WX[r];
    }
    __shared__ float red[3 * RPB][NWARPS];
    const int lane = tid & 31, warp = tid >> 5;
    #pragma unroll
    for (int i = 0; i < 3 * RPB; i++) {
        float vv = acc[i];
        #pragma unroll
        for (int o = 16; o > 0; o >>= 1) vv += __shfl_down_sync(0xffffffffu, vv, o);
        if (lane == 0) red[i][warp] = vv;
    }
    __syncthreads();
    if (tid < 3 * RPB) {
        float vv = 0.f;
        #pragma unroll
        for (int wi = 0; wi < NWARPS; wi++) vv += red[tid][wi];
        const int r     = tid / 3;
        const int which = tid % 3;
        const int idx   = (row0 + r) * SPLIT + ch;
        if      (which == 0) d_pZ[idx] = vv;
        else if (which == 1) d_pS[idx] = vv;
        else                 d_pW[idx] = vv;
    }

    // ---- Last block reduces everything ----
    __shared__ bool isLast;
    __syncthreads();
    if (tid == 0) {
        __threadfence();
        unsigned int t = atomicAdd(&d_ctr, 1u);
        isLast = (t == (unsigned int)(GRID - 1));
    }
    __syncthreads();

    if (isLast) {
        float v = 0.f;
        #pragma unroll
        for (int half = 0; half < B_ROWS / THREADS; half++) {   // 4 rows/thread
            const int b = tid + half * THREADS;
            float Zt = 0.f, St = 0.f, Wt = 0.f;
            #pragma unroll
            for (int cc = 0; cc < SPLIT; cc++) {
                Zt += __ldcg(&d_pZ[b * SPLIT + cc]);
                St += __ldcg(&d_pS[b * SPLIT + cc]);
                Wt += __ldcg(&d_pW[b * SPLIT + cc]);
            }
            v += logf(Zt) - Wt * __fdividef(1.0f, St);
        }
        __shared__ float fin[NWARPS];
        #pragma unroll
        for (int o = 16; o > 0; o >>= 1) v += __shfl_down_sync(0xffffffffu, v, o);
        if (lane == 0) fin[warp] = v;
        __syncthreads();
        if (tid == 0) {
            float s = 0.f;
            #pragma unroll
            for (int i = 0; i < NWARPS; i++) s += fin[i];
            out[0] = s * (1.0f / (float)B_ROWS);
            d_ctr  = 0;   // reset for graph replay
        }
    }
}

extern "C" void kernel_launch(void* const* d_in, const int* in_sizes, int n_in,
                              void* d_out, int out_size) {
    const float* logits = (const float*)d_in[0];   // [512, 32768]
    const float* latlon = (const float*)d_in[1];   // [512, 2]
    const float* geo    = (const float*)d_in[2];   // [32768, 2]

    precompute<<<(C_CELLS + 255) / 256, 256>>>(geo, latlon);
    main_kernel<<<GRID, THREADS>>>(logits, (float*)d_out);
}

// round 12
// speedup vs baseline: 1.0115x; 1.0115x over previous
#include <cuda_runtime.h>

// HaversineSmoothedLoss — single launch: in-kernel celltab build + grid spin
// barrier (co-resident grid: 512 blocks <= 592 slots at 4 blocks/SM) + R9 loop.
//   a  = (1 - u1·u2)/2             (unit 3-vectors; no per-pair trig)
//   w  = exp2( sqrt(|a|) * (KL + KL3*a) )   1-term asin correction
//   loss_b = log(Z_b) - (Σ w·x)/S_b ,  Z = Σ e^x, S = Σ w
//
// Phase 0: block bx computes celltab cells [bx*64, bx*64+64) (zero redundancy)
//          and row-normal bx. Grid barrier (threadfence + counter + spin).
// Phase 1: 512 blocks (256 thr) = 128 row-groups (4 rows) × 4 chunks (8192
//          cells), 8 iters/thread, 7 front-batched LDG.128/iter, branchless.
// Phase 2: last block (2nd arrival counter) reduces partials, resets counters.

#define C_CELLS 32768
#define B_ROWS  512
#define RPB     4
#define SPLIT   4
#define CHUNK   (C_CELLS / SPLIT)          // 8192
#define THREADS 256
#define NWARPS  (THREADS / 32)             // 8
#define ITERS   (CHUNK / (4 * THREADS))    // 8
#define GRID    ((B_ROWS / RPB) * SPLIT)   // 512
#define CELLS_PER_BLOCK (C_CELLS / GRID)   // 64

__device__ float d_ux[C_CELLS];
__device__ float d_uy[C_CELLS];
__device__ float d_uz[C_CELLS];
__device__ float d_prow[3][B_ROWS];        // -0.5 * row unit vectors
__device__ float d_pZ[B_ROWS * SPLIT];
__device__ float d_pS[B_ROWS * SPLIT];
__device__ float d_pW[B_ROWS * SPLIT];
__device__ unsigned int d_start = 0;       // phase-0 barrier counter
__device__ unsigned int d_ctr   = 0;       // completion counter

__device__ __forceinline__ float fsqrt_ap(float a) {
    float r; asm("sqrt.approx.f32 %0, %1;" : "=f"(r) : "f"(a)); return r;
}
__device__ __forceinline__ float fexp2_ap(float a) {
    float r; asm("ex2.approx.f32 %0, %1;" : "=f"(r) : "f"(a)); return r;
}

__global__ __launch_bounds__(THREADS, 4)
void fused_kernel(const float* __restrict__ logits,
                  const float* __restrict__ latlon,
                  const float* __restrict__ geo,
                  float* __restrict__ out) {
    const int bx    = blockIdx.x;
    const int rg    = bx >> 2;             // row group 0..127
    const int ch    = bx & (SPLIT - 1);    // chunk 0..3
    const int row0  = rg * RPB;
    const int tid   = threadIdx.x;
    const int qbase = (ch * CHUNK) >> 2;   // float4 quad base of this chunk

    const float d2r   = 0.017453292519943295f;
    const float LOG2E = 1.4426950408889634f;
    const float KL  = -245.104328f;        // -(2*6371/75)*log2(e)
    const float KL3 = -40.8507213f;        // KL/6 (imm multiplier -> FFMA-imm)

    // ---- Phase 0: build this block's 64 celltab entries + 1 row normal ----
    if (tid < CELLS_PER_BLOCK) {
        const int c = bx * CELLS_PER_BLOCK + tid;
        float lat = geo[2 * c]     * d2r;
        float lon = geo[2 * c + 1] * d2r;
        float sl, cl, so, co;
        sincosf(lat, &sl, &cl);
        sincosf(lon, &so, &co);
        d_ux[c] = sl;
        d_uy[c] = cl * so;
        d_uz[c] = cl * co;
    } else if (tid == CELLS_PER_BLOCK) {   // one row normal per block (bx < 512)
        float lat = latlon[2 * bx]     * d2r;
        float lon = latlon[2 * bx + 1] * d2r;
        float sl, cl, so, co;
        sincosf(lat, &sl, &cl);
        sincosf(lon, &so, &co);
        d_prow[0][bx] = -0.5f * sl;
        d_prow[1][bx] = -0.5f * cl * so;
        d_prow[2][bx] = -0.5f * cl * co;
    }
    __syncthreads();

    // Grid-wide barrier (grid is co-resident: 512 blocks <= 592 slots).
    if (tid == 0) {
        __threadfence();
        atomicAdd(&d_start, 1u);
        while (atomicAdd(&d_start, 0u) < (unsigned int)GRID)
            __nanosleep(64);
    }
    __syncthreads();

    // ---- Phase 1: fused pass (R9 loop, unchanged) ----
    float nx[RPB], ny[RPB], nz[RPB];
    #pragma unroll
    for (int r = 0; r < RPB; r++) {
        nx[r] = d_prow[0][row0 + r];
        ny[r] = d_prow[1][row0 + r];
        nz[r] = d_prow[2][row0 + r];
    }

    const float4* __restrict__ lg4 = (const float4*)logits;
    const float4* __restrict__ ux4 = (const float4*)d_ux;
    const float4* __restrict__ uy4 = (const float4*)d_uy;
    const float4* __restrict__ uz4 = (const float4*)d_uz;

    float Z[RPB], S[RPB], WX[RPB];
    #pragma unroll
    for (int r = 0; r < RPB; r++) { Z[r] = 0.f; S[r] = 0.f; WX[r] = 0.f; }

    #pragma unroll 1
    for (int it = 0; it < ITERS; it++) {
        const int q = qbase + it * THREADS + tid;

        float4 xr[RPB];
        #pragma unroll
        for (int r = 0; r < RPB; r++)
            xr[r] = __ldg(lg4 + (size_t)(row0 + r) * (C_CELLS / 4) + q);
        const float4 gx = __ldg(ux4 + q);
        const float4 gy = __ldg(uy4 + q);
        const float4 gz = __ldg(uz4 + q);

        const float gxs[4] = {gx.x, gx.y, gx.z, gx.w};
        const float gys[4] = {gy.x, gy.y, gy.z, gy.w};
        const float gzs[4] = {gz.x, gz.y, gz.z, gz.w};

        #pragma unroll
        for (int r = 0; r < RPB; r++) {
            const float xs[4] = {xr[r].x, xr[r].y, xr[r].z, xr[r].w};
            #pragma unroll
            for (int k = 0; k < 4; k++) {
                const float x = xs[k];
                Z[r] += fexp2_ap(x * LOG2E);
                float a = fmaf(nx[r], gxs[k], fmaf(ny[r], gys[k], fmaf(nz[r], gzs[k], 0.5f)));
                float s  = fsqrt_ap(fabsf(a));
                float qq = fmaf(a, KL3, KL);
                float w  = fexp2_ap(s * qq);     // underflows to 0 for far cells
                S[r]  += w;
                WX[r]  = fmaf(w, x, WX[r]);
            }
        }
    }

    // ---- Block reduction of 12 accumulators (deterministic tree) ----
    float acc[3 * RPB];
    #pragma unroll
    for (int r = 0; r < RPB; r++) {
        acc[r * 3 + 0] = Z[r]; acc[r * 3 + 1] = S[r]; acc[r * 3 + 2] = WX[r];
    }
    __shared__ float red[3 * RPB][NWARPS];
    const int lane = tid & 31, warp = tid >> 5;
    #pragma unroll
    for (int i = 0; i < 3 * RPB; i++) {
        float vv = acc[i];
        #pragma unroll
        for (int o = 16; o > 0; o >>= 1) vv += __shfl_down_sync(0xffffffffu, vv, o);
        if (lane == 0) red[i][warp] = vv;
    }
    __syncthreads();
    if (tid < 3 * RPB) {
        float vv = 0.f;
        #pragma unroll
        for (int wi = 0; wi < NWARPS; wi++) vv += red[tid][wi];
        const int r     = tid / 3;
        const int which = tid % 3;
        const int idx   = (row0 + r) * SPLIT + ch;
        if      (which == 0) d_pZ[idx] = vv;
        else if (which == 1) d_pS[idx] = vv;
        else                 d_pW[idx] = vv;
    }

    // ---- Phase 2: last block reduces everything ----
    __shared__ bool isLast;
    __syncthreads();
    if (tid == 0) {
        __threadfence();
        unsigned int t = atomicAdd(&d_ctr, 1u);
        isLast = (t == (unsigned int)(GRID - 1));
    }
    __syncthreads();

    if (isLast) {
        float v = 0.f;
        #pragma unroll
        for (int half = 0; half < B_ROWS / THREADS; half++) {   // 2 rows/thread
            const int b = tid + half * THREADS;
            float Zt = 0.f, St = 0.f, Wt = 0.f;
            #pragma unroll
            for (int cc = 0; cc < SPLIT; cc++) {
                Zt += __ldcg(&d_pZ[b * SPLIT + cc]);
                St += __ldcg(&d_pS[b * SPLIT + cc]);
                Wt += __ldcg(&d_pW[b * SPLIT + cc]);
            }
            v += logf(Zt) - Wt * __fdividef(1.0f, St);
        }
        __shared__ float fin[NWARPS];
        #pragma unroll
        for (int o = 16; o > 0; o >>= 1) v += __shfl_down_sync(0xffffffffu, v, o);
        if (lane == 0) fin[warp] = v;
        __syncthreads();
        if (tid == 0) {
            float s = 0.f;
            #pragma unroll
            for (int i = 0; i < NWARPS; i++) s += fin[i];
            out[0] = s * (1.0f / (float)B_ROWS);
            d_ctr   = 0;     // reset for graph replay (all blocks are past both
            d_start = 0;     // barriers once the last one reaches here)
        }
    }
}

extern "C" void kernel_launch(void* const* d_in, const int* in_sizes, int n_in,
                              void* d_out, int out_size) {
    const float* logits = (const float*)d_in[0];   // [512, 32768]
    const float* latlon = (const float*)d_in[1];   // [512, 2]
    const float* geo    = (const float*)d_in[2];   // [32768, 2]

    fused_kernel<<<GRID, THREADS>>>(logits, latlon, geo, (float*)d_out);
}

// round 13
// speedup vs baseline: 1.1000x; 1.0875x over previous
#include <cuda_runtime.h>

// HaversineSmoothedLoss — R9 structure + instruction diet v2.
//   a  = (1 - u1·u2)/2            (unit 3-vectors; no per-pair trig)
//   w  = exp2( -sqrt(|a*K^2|) )   K = (2*6371/75)*log2(e); asin correction dropped
//        (distance error <= a/6 ~ 1.2e-4 on weight-relevant cells)
//   loss_b = log(Z_b) - (Σ w·x)/S_b ,  Z = Σ e^x, S = Σ w
//
// K0: interleaved celltab [gx4,gy4,gz4] per quad (48B stride) + row normals.
// K1: 512 blocks (256 thr) = 128 row-groups (4 rows) × 4 chunks (8192 cells),
//     8 iters/thread, 7 front-batched LDG.128/iter via advancing pointers,
//     branchless 11-inst/elem loop. Last block reduces partials.

#define C_CELLS 32768
#define B_ROWS  512
#define RPB     4
#define SPLIT   4
#define CHUNK   (C_CELLS / SPLIT)          // 8192
#define THREADS 256
#define NWARPS  (THREADS / 32)             // 8
#define ITERS   (CHUNK / (4 * THREADS))    // 8
#define GRID    ((B_ROWS / RPB) * SPLIT)   // 512

__device__ float4 d_ct[(C_CELLS / 4) * 3]; // interleaved: quad q -> [3q]=gx,[3q+1]=gy,[3q+2]=gz
__device__ float  d_prow[3][B_ROWS];       // -0.5 * row unit vectors
__device__ float  d_pZ[B_ROWS * SPLIT];
__device__ float  d_pS[B_ROWS * SPLIT];
__device__ float  d_pW[B_ROWS * SPLIT];
__device__ unsigned int d_ctr = 0;

__device__ __forceinline__ float fsqrt_ap(float a) {
    float r; asm("sqrt.approx.f32 %0, %1;" : "=f"(r) : "f"(a)); return r;
}
__device__ __forceinline__ float fexp2_ap(float a) {
    float r; asm("ex2.approx.f32 %0, %1;" : "=f"(r) : "f"(a)); return r;
}

__global__ void precompute(const float* __restrict__ geo,
                           const float* __restrict__ latlon) {
    const float d2r = 0.017453292519943295f;
    int i = blockIdx.x * blockDim.x + threadIdx.x;
    if (i < C_CELLS) {
        float lat = geo[2 * i]     * d2r;
        float lon = geo[2 * i + 1] * d2r;
        float sl, cl, so, co;
        sincosf(lat, &sl, &cl);
        sincosf(lon, &so, &co);
        const int q = i >> 2, k = i & 3;
        float* ct = (float*)d_ct;
        ct[q * 12 + 0 + k] = sl;        // gx
        ct[q * 12 + 4 + k] = cl * so;   // gy
        ct[q * 12 + 8 + k] = cl * co;   // gz
    }
    if (i < B_ROWS) {
        float lat = latlon[2 * i]     * d2r;
        float lon = latlon[2 * i + 1] * d2r;
        float sl, cl, so, co;
        sincosf(lat, &sl, &cl);
        sincosf(lon, &so, &co);
        d_prow[0][i] = -0.5f * sl;
        d_prow[1][i] = -0.5f * cl * so;
        d_prow[2][i] = -0.5f * cl * co;
    }
}

__global__ __launch_bounds__(THREADS, 4)
void main_kernel(const float* __restrict__ logits,
                 float* __restrict__ out) {
    const int bx    = blockIdx.x;
    const int rg    = bx >> 2;             // row group 0..127
    const int ch    = bx & (SPLIT - 1);    // chunk 0..3
    const int row0  = rg * RPB;
    const int tid   = threadIdx.x;
    const int q0    = ((ch * CHUNK) >> 2) + tid;   // this thread's first quad

    const float LOG2E = 1.4426950408889634f;
    const float KL2   = 60076.13f;         // ((2*6371/75)*log2(e))^2

    // Row uniforms (block-uniform loads).
    float nx[RPB], ny[RPB], nz[RPB];
    #pragma unroll
    for (int r = 0; r < RPB; r++) {
        nx[r] = d_prow[0][row0 + r];
        ny[r] = d_prow[1][row0 + r];
        nz[r] = d_prow[2][row0 + r];
    }

    // Advancing pointers: constant strides, loop-invariant address math.
    const float4* __restrict__ pct = d_ct + (size_t)q0 * 3;
    const float4* __restrict__ plg = (const float4*)logits + (size_t)row0 * (C_CELLS / 4) + q0;

    float Z[RPB], S[RPB], WX[RPB];
    #pragma unroll
    for (int r = 0; r < RPB; r++) { Z[r] = 0.f; S[r] = 0.f; WX[r] = 0.f; }

    #pragma unroll 1
    for (int it = 0; it < ITERS; it++) {
        // Front-batch all 7 LDG.128 (rows at fixed 8192-quad strides).
        float4 xr[RPB];
        #pragma unroll
        for (int r = 0; r < RPB; r++)
            xr[r] = __ldg(plg + (size_t)r * (C_CELLS / 4));
        const float4 gx = __ldg(pct + 0);
        const float4 gy = __ldg(pct + 1);
        const float4 gz = __ldg(pct + 2);
        pct += 3 * THREADS;
        plg += THREADS;

        const float gxs[4] = {gx.x, gx.y, gx.z, gx.w};
        const float gys[4] = {gy.x, gy.y, gy.z, gy.w};
        const float gzs[4] = {gz.x, gz.y, gz.z, gz.w};

        #pragma unroll
        for (int r = 0; r < RPB; r++) {
            const float xs[4] = {xr[r].x, xr[r].y, xr[r].z, xr[r].w};
            #pragma unroll
            for (int k = 0; k < 4; k++) {
                const float x = xs[k];
                Z[r] += fexp2_ap(x * LOG2E);
                float a = fmaf(nx[r], gxs[k], fmaf(ny[r], gys[k], fmaf(nz[r], gzs[k], 0.5f)));
                float t = a * KL2;                   // FMUL-imm (rt 1)
                float s = fsqrt_ap(fabsf(t));        // |t|: free MUFU modifier
                float w = fexp2_ap(-s);              // neg folded into MUFU operand
                S[r]  += w;
                WX[r]  = fmaf(w, x, WX[r]);
            }
        }
    }

    // ---- Block reduction of 12 accumulators (deterministic tree) ----
    float acc[3 * RPB];
    #pragma unroll
    for (int r = 0; r < RPB; r++) {
        acc[r * 3 + 0] = Z[r]; acc[r * 3 + 1] = S[r]; acc[r * 3 + 2] = WX[r];
    }
    __shared__ float red[3 * RPB][NWARPS];
    const int lane = tid & 31, warp = tid >> 5;
    #pragma unroll
    for (int i = 0; i < 3 * RPB; i++) {
        float vv = acc[i];
        #pragma unroll
        for (int o = 16; o > 0; o >>= 1) vv += __shfl_down_sync(0xffffffffu, vv, o);
        if (lane == 0) red[i][warp] = vv;
    }
    __syncthreads();
    if (tid < 3 * RPB) {
        float vv = 0.f;
        #pragma unroll
        for (int wi = 0; wi < NWARPS; wi++) vv += red[tid][wi];
        const int r     = tid / 3;
        const int which = tid % 3;
        const int idx   = (row0 + r) * SPLIT + ch;
        if      (which == 0) d_pZ[idx] = vv;
        else if (which == 1) d_pS[idx] = vv;
        else                 d_pW[idx] = vv;
    }

    // ---- Last block reduces everything ----
    __shared__ bool isLast;
    __syncthreads();
    if (tid == 0) {
        __threadfence();
        unsigned int t = atomicAdd(&d_ctr, 1u);
        isLast = (t == (unsigned int)(GRID - 1));
    }
    __syncthreads();

    if (isLast) {
        float v = 0.f;
        #pragma unroll
        for (int half = 0; half < B_ROWS / THREADS; half++) {   // 2 rows/thread
            const int b = tid + half * THREADS;
            float Zt = 0.f, St = 0.f, Wt = 0.f;
            #pragma unroll
            for (int cc = 0; cc < SPLIT; cc++) {
                Zt += __ldcg(&d_pZ[b * SPLIT + cc]);
                St += __ldcg(&d_pS[b * SPLIT + cc]);
                Wt += __ldcg(&d_pW[b * SPLIT + cc]);
            }
            v += logf(Zt) - Wt * __fdividef(1.0f, St);
        }
        __shared__ float fin[NWARPS];
        #pragma unroll
        for (int o = 16; o > 0; o >>= 1) v += __shfl_down_sync(0xffffffffu, v, o);
        if (lane == 0) fin[warp] = v;
        __syncthreads();
        if (tid == 0) {
            float s = 0.f;
            #pragma unroll
            for (int i = 0; i < NWARPS; i++) s += fin[i];
            out[0] = s * (1.0f / (float)B_ROWS);
            d_ctr  = 0;   // reset for graph replay
        }
    }
}

extern "C" void kernel_launch(void* const* d_in, const int* in_sizes, int n_in,
                              void* d_out, int out_size) {
    const float* logits = (const float*)d_in[0];   // [512, 32768]
    const float* latlon = (const float*)d_in[1];   // [512, 2]
    const float* geo    = (const float*)d_in[2];   // [32768, 2]

    precompute<<<(C_CELLS + 255) / 256, 256>>>(geo, latlon);
    main_kernel<<<GRID, THREADS>>>(logits, (float*)d_out);
}